// round 2
// baseline (speedup 1.0000x reference)
#include <cuda_runtime.h>
#include <cuda_bf16.h>
#include <cstdint>

// Problem constants
#define HH 96
#define WW 96
#define CC 256
#define OHW 94
#define QN 8836          // number of patches (both synth and style)
#define QPAD 8960        // 70 * 128
#define NTILE 70
#define DD 2304          // 256 * 9

// Scratch (static device globals — allowed; no runtime allocation)
__device__ __nv_bfloat16 g_A[(size_t)QPAD * DD];   // synth patches, bf16
__device__ __nv_bfloat16 g_B[(size_t)QPAD * DD];   // style patches, bf16
__device__ float g_invnorm[QPAD];
__device__ unsigned long long g_part[(size_t)NTILE * QPAD]; // per-(ntile,q) packed best
__device__ float g_loss[QN];

// ---------------------------------------------------------------------------
// K0: build bf16 patch matrices + style inverse norms (fp32-accurate)
// Patch layout: d = c*9 + (kh*3+kw). Any consistent ordering is valid since the
// loss only uses dot products / elementwise diffs.
// ---------------------------------------------------------------------------
__global__ void prep_kernel(const float* __restrict__ inp, const float* __restrict__ tgt) {
    int q = blockIdx.x;           // 0..QPAD-1
    int tid = threadIdx.x;        // 256 threads
    bool valid = q < QN;
    int i = valid ? (q / OHW) : 0;
    int j = valid ? (q % OHW) : 0;
    float ss = 0.f;
    size_t rb = (size_t)q * DD;
#pragma unroll
    for (int it = 0; it < 9; ++it) {
        int d = it * 256 + tid;
        float av = 0.f, bv = 0.f;
        if (valid) {
            int c = d / 9, t = d - c * 9;
            int off = c * (HH * WW) + (i + t / 3) * WW + (j + t % 3);
            av = inp[off];
            bv = tgt[off];
        }
        g_A[rb + d] = __float2bfloat16(av);
        g_B[rb + d] = __float2bfloat16(bv);
        ss += bv * bv;
    }
    __shared__ float red[256];
    red[tid] = ss;
    __syncthreads();
    for (int s = 128; s > 0; s >>= 1) {
        if (tid < s) red[tid] += red[tid + s];
        __syncthreads();
    }
    if (tid == 0) g_invnorm[q] = valid ? (1.0f / sqrtf(red[0])) : 1.0f;
}

// ---------------------------------------------------------------------------
// K1: 8836x8836x2304 bf16 GEMM (A*B^T) with fused per-row scaled argmax.
// Tiles: 128x128x32, 256 threads (8 warps, 4x2), warp tile 32x64.
// SMEM rows padded to 40 bf16 (80 B) => conflict-free ldmatrix ((5r+c)%8 distinct).
// ---------------------------------------------------------------------------
__device__ __forceinline__ void cpa16(void* s, const void* g) {
    uint32_t sa = (uint32_t)__cvta_generic_to_shared(s);
    asm volatile("cp.async.cg.shared.global [%0], [%1], 16;" :: "r"(sa), "l"(g));
}
__device__ __forceinline__ void ldsm4(uint32_t* r, const __nv_bfloat16* p) {
    uint32_t sa = (uint32_t)__cvta_generic_to_shared(p);
    asm volatile("ldmatrix.sync.aligned.m8n8.x4.shared.b16 {%0,%1,%2,%3}, [%4];"
                 : "=r"(r[0]), "=r"(r[1]), "=r"(r[2]), "=r"(r[3]) : "r"(sa));
}
__device__ __forceinline__ void ldsm2(uint32_t* r, const __nv_bfloat16* p) {
    uint32_t sa = (uint32_t)__cvta_generic_to_shared(p);
    asm volatile("ldmatrix.sync.aligned.m8n8.x2.shared.b16 {%0,%1}, [%2];"
                 : "=r"(r[0]), "=r"(r[1]) : "r"(sa));
}
__device__ __forceinline__ void mma16816(float* c, const uint32_t* a, const uint32_t* b) {
    asm volatile(
        "mma.sync.aligned.m16n8k16.row.col.f32.bf16.bf16.f32 "
        "{%0,%1,%2,%3}, {%4,%5,%6,%7}, {%8,%9}, {%0,%1,%2,%3};"
        : "+f"(c[0]), "+f"(c[1]), "+f"(c[2]), "+f"(c[3])
        : "r"(a[0]), "r"(a[1]), "r"(a[2]), "r"(a[3]), "r"(b[0]), "r"(b[1]));
}

__global__ __launch_bounds__(256) void gemm_argmax_kernel() {
    __shared__ __align__(16) __nv_bfloat16 sA[2][128 * 40];
    __shared__ __align__(16) __nv_bfloat16 sB[2][128 * 40];
    const int mt = blockIdx.y, nt = blockIdx.x;
    const int tid = threadIdx.x;
    const int lane = tid & 31, warp = tid >> 5;
    const int wm = warp >> 1, wn = warp & 1;

    float acc[2][8][4];
#pragma unroll
    for (int a = 0; a < 2; a++)
#pragma unroll
        for (int b = 0; b < 8; b++)
#pragma unroll
            for (int c = 0; c < 4; c++) acc[a][b][c] = 0.f;

    // tile loader: 128 rows x 32 cols bf16, 16B chunks; 512 chunks / 256 threads
    auto load_tiles = [&](int buf, int k0) {
#pragma unroll
        for (int u = 0; u < 2; ++u) {
            int ch = tid + u * 256;
            int row = ch >> 2, c4 = ch & 3;
            const __nv_bfloat16* ga = g_A + (size_t)(mt * 128 + row) * DD + k0 + c4 * 8;
            const __nv_bfloat16* gb = g_B + (size_t)(nt * 128 + row) * DD + k0 + c4 * 8;
            cpa16(&sA[buf][row * 40 + c4 * 8], ga);
            cpa16(&sB[buf][row * 40 + c4 * 8], gb);
        }
        asm volatile("cp.async.commit_group;");
    };

    load_tiles(0, 0);
    const int NKI = DD / 32;  // 72
    for (int kk = 0; kk < NKI; ++kk) {
        int buf = kk & 1;
        if (kk + 1 < NKI) {
            load_tiles(buf ^ 1, (kk + 1) * 32);
            asm volatile("cp.async.wait_group 1;");
        } else {
            asm volatile("cp.async.wait_group 0;");
        }
        __syncthreads();
#pragma unroll
        for (int ks = 0; ks < 2; ++ks) {
            uint32_t afr[2][4];
#pragma unroll
            for (int mi = 0; mi < 2; ++mi) {
                int r = wm * 32 + mi * 16 + (lane & 7) + ((lane >> 3) & 1) * 8;
                int cch = ks * 2 + (lane >> 4);
                ldsm4(afr[mi], &sA[buf][r * 40 + cch * 8]);
            }
            uint32_t bfr[8][2];
#pragma unroll
            for (int ni = 0; ni < 8; ++ni) {
                int l = lane & 15;
                int r = wn * 64 + ni * 8 + (l & 7);
                int cch = ks * 2 + ((l >> 3) & 1);
                ldsm2(bfr[ni], &sB[buf][r * 40 + cch * 8]);
            }
#pragma unroll
            for (int mi = 0; mi < 2; ++mi)
#pragma unroll
                for (int ni = 0; ni < 8; ++ni)
                    mma16816(acc[mi][ni], afr[mi], bfr[ni]);
        }
        __syncthreads();
    }

    // Epilogue: per-row argmax of resp = dot * invnorm[s] over this 128-col strip.
    // Packed key: (sortable(resp) << 32) | (~s) so max() picks largest resp,
    // smallest s on exact ties (matches jnp.argmax first-max semantics).
    float inl[16];
    const int sbase = nt * 128 + wn * 64;
#pragma unroll
    for (int ni = 0; ni < 8; ++ni)
#pragma unroll
        for (int cc = 0; cc < 2; ++cc) {
            int s = sbase + ni * 8 + (lane & 3) * 2 + cc;
            inl[ni * 2 + cc] = (s < QPAD) ? g_invnorm[s] : 1.0f;
        }

    unsigned long long* red = reinterpret_cast<unsigned long long*>(&sA[0][0]);
#pragma unroll
    for (int mi = 0; mi < 2; ++mi) {
#pragma unroll
        for (int h = 0; h < 2; ++h) {
            unsigned long long key = 0ull;
#pragma unroll
            for (int ni = 0; ni < 8; ++ni) {
#pragma unroll
                for (int cc = 0; cc < 2; ++cc) {
                    int s = sbase + ni * 8 + (lane & 3) * 2 + cc;
                    if (s < QN) {
                        float resp = acc[mi][ni][h * 2 + cc] * inl[ni * 2 + cc];
                        uint32_t uu = __float_as_uint(resp);
                        uu ^= (uu >> 31) ? 0xFFFFFFFFu : 0x80000000u;
                        unsigned long long k =
                            ((unsigned long long)uu << 32) |
                            (unsigned long long)(0xFFFFFFFFu - (uint32_t)s);
                        if (k > key) key = k;
                    }
                }
            }
#pragma unroll
            for (int off = 1; off < 4; off <<= 1) {
                unsigned long long o = __shfl_xor_sync(0xFFFFFFFFu, key, off);
                if (o > key) key = o;
            }
            if ((lane & 3) == 0) {
                int rl = wm * 32 + mi * 16 + (lane >> 2) + h * 8;
                red[rl * 2 + wn] = key;
            }
        }
    }
    __syncthreads();
    if (tid < 128) {
        unsigned long long k0 = red[tid * 2], k1 = red[tid * 2 + 1];
        g_part[(size_t)nt * QPAD + (size_t)mt * 128 + tid] = (k0 > k1) ? k0 : k1;
    }
}

// ---------------------------------------------------------------------------
// K2: reduce 70 partials per q -> nn index; exact fp32 gathered MSE from the
// raw images (so GEMM precision never touches the loss value).
// ---------------------------------------------------------------------------
__global__ void loss_kernel(const float* __restrict__ inp, const float* __restrict__ tgt) {
    int q = blockIdx.x;       // < QN
    int tid = threadIdx.x;    // 256
    __shared__ unsigned long long sk[256];
    unsigned long long k = 0ull;
    if (tid < NTILE) k = g_part[(size_t)tid * QPAD + q];
    sk[tid] = k;
    __syncthreads();
    for (int s = 128; s > 0; s >>= 1) {
        if (tid < s) { if (sk[tid + s] > sk[tid]) sk[tid] = sk[tid + s]; }
        __syncthreads();
    }
    int snn = (int)(0xFFFFFFFFu - (uint32_t)(sk[0] & 0xFFFFFFFFull));
    int i = q / OHW, j = q % OHW;
    int u = snn / OHW, v = snn % OHW;
    float sum = 0.f;
#pragma unroll
    for (int it = 0; it < 9; ++it) {
        int d = it * 256 + tid;
        int c = d / 9, t = d - c * 9;
        int oa = c * (HH * WW) + (i + t / 3) * WW + (j + t % 3);
        int ob = c * (HH * WW) + (u + t / 3) * WW + (v + t % 3);
        float df = inp[oa] - tgt[ob];
        sum += df * df;
    }
    __shared__ float red[256];
    red[tid] = sum;
    __syncthreads();
    for (int s = 128; s > 0; s >>= 1) {
        if (tid < s) red[tid] += red[tid + s];
        __syncthreads();
    }
    if (tid == 0) g_loss[q] = red[0];
}

// K3: deterministic scalar reduce -> loss = sum / (QN * DD)
__global__ void final_kernel(float* __restrict__ out) {
    __shared__ float red[256];
    int tid = threadIdx.x;
    float acc = 0.f;
    for (int i = tid; i < QN; i += 256) acc += g_loss[i];
    red[tid] = acc;
    __syncthreads();
    for (int s = 128; s > 0; s >>= 1) {
        if (tid < s) red[tid] += red[tid + s];
        __syncthreads();
    }
    if (tid == 0) out[0] = red[0] / ((float)QN * (float)DD);
}

extern "C" void kernel_launch(void* const* d_in, const int* in_sizes, int n_in,
                              void* d_out, int out_size) {
    const float* inp = (const float*)d_in[0];   // input
    const float* tgt = (const float*)d_in[1];   // target
    float* out = (float*)d_out;

    prep_kernel<<<QPAD, 256>>>(inp, tgt);
    dim3 g(NTILE, NTILE);
    gemm_argmax_kernel<<<g, 256>>>();
    loss_kernel<<<QN, 256>>>(inp, tgt);
    final_kernel<<<1, 256>>>(out);
}

// round 4
// speedup vs baseline: 2.8250x; 2.8250x over previous
#include <cuda_runtime.h>
#include <cuda_bf16.h>
#include <cstdint>

// Problem constants
#define HH 96
#define WW 96
#define NPIX 9216          // 96*96
#define OHW 94
#define QN 8836            // 94*94 patches on each side
#define CCH 256            // channels = GEMM K
#define MTIL 72            // 9216 / 128

// Static device scratch (no runtime allocation)
__device__ __nv_bfloat16 g_Xt[(size_t)NPIX * CCH];   // inp transposed  [pix][c] bf16
__device__ __nv_bfloat16 g_Yt[(size_t)NPIX * CCH];   // tgt transposed  [pix][c] bf16
__device__ float g_P[(size_t)NPIX * NPIX + 256];     // pixel Gram matrix (+tap-read pad)
__device__ float g_invY[NPIX];                       // 1/style_norm indexed by y (0 if invalid)
__device__ int   g_nn[QN];
__device__ float g_loss[QN];

// ---------------------------------------------------------------------------
// K0: transpose+convert images: [256][9216] fp32 -> [9216][256] bf16
// ---------------------------------------------------------------------------
__global__ void transpose_kernel(const float* __restrict__ inp, const float* __restrict__ tgt) {
    __shared__ float t[32][33];
    const float* src = blockIdx.z ? tgt : inp;
    __nv_bfloat16* dst = blockIdx.z ? g_Yt : g_Xt;
    int p0 = blockIdx.x * 32, c0 = blockIdx.y * 32;
    int tx = threadIdx.x & 31, ty = threadIdx.x >> 5;  // 32 x 8
#pragma unroll
    for (int r = 0; r < 4; ++r) {
        int c = c0 + ty + r * 8;
        t[ty + r * 8][tx] = src[(size_t)c * NPIX + p0 + tx];
    }
    __syncthreads();
#pragma unroll
    for (int r = 0; r < 4; ++r) {
        int p = p0 + ty + r * 8;
        dst[(size_t)p * CCH + c0 + tx] = __float2bfloat16(t[tx][ty + r * 8]);
    }
}

// ---------------------------------------------------------------------------
// K0b: style patch inverse norms -> g_invY[y], y = u*96+v (0 elsewhere; the
// array is zero-initialized at module load and invalid slots are never written)
// ---------------------------------------------------------------------------
__global__ void invnorm_kernel() {
    int q = blockIdx.x;            // 0..QN-1
    int tid = threadIdx.x;         // 256 = one channel each
    int u = q / OHW, v = q % OHW;
    int y = u * WW + v;
    float ss = 0.f;
#pragma unroll
    for (int t = 0; t < 9; ++t) {
        int pix = y + (t / 3) * WW + (t % 3);
        float val = __bfloat162float(g_Yt[(size_t)pix * CCH + tid]);
        ss += val * val;
    }
    __shared__ float red[256];
    red[tid] = ss;
    __syncthreads();
    for (int s = 128; s > 0; s >>= 1) {
        if (tid < s) red[tid] += red[tid + s];
        __syncthreads();
    }
    if (tid == 0) g_invY[y] = 1.0f / sqrtf(red[0]);
}

// ---------------------------------------------------------------------------
// K1: P = Xt * Yt^T  (9216x9216x256 bf16 -> fp32). Validated round-1 HMMA
// pipeline: 128x128 tile, k-chunk 32, double-buffered cp.async, 8 warps.
// ---------------------------------------------------------------------------
__device__ __forceinline__ void cpa16(void* s, const void* g) {
    uint32_t sa = (uint32_t)__cvta_generic_to_shared(s);
    asm volatile("cp.async.cg.shared.global [%0], [%1], 16;" :: "r"(sa), "l"(g));
}
__device__ __forceinline__ void ldsm4(uint32_t* r, const __nv_bfloat16* p) {
    uint32_t sa = (uint32_t)__cvta_generic_to_shared(p);
    asm volatile("ldmatrix.sync.aligned.m8n8.x4.shared.b16 {%0,%1,%2,%3}, [%4];"
                 : "=r"(r[0]), "=r"(r[1]), "=r"(r[2]), "=r"(r[3]) : "r"(sa));
}
__device__ __forceinline__ void ldsm2(uint32_t* r, const __nv_bfloat16* p) {
    uint32_t sa = (uint32_t)__cvta_generic_to_shared(p);
    asm volatile("ldmatrix.sync.aligned.m8n8.x2.shared.b16 {%0,%1}, [%2];"
                 : "=r"(r[0]), "=r"(r[1]) : "r"(sa));
}
__device__ __forceinline__ void mma16816(float* c, const uint32_t* a, const uint32_t* b) {
    asm volatile(
        "mma.sync.aligned.m16n8k16.row.col.f32.bf16.bf16.f32 "
        "{%0,%1,%2,%3}, {%4,%5,%6,%7}, {%8,%9}, {%0,%1,%2,%3};"
        : "+f"(c[0]), "+f"(c[1]), "+f"(c[2]), "+f"(c[3])
        : "r"(a[0]), "r"(a[1]), "r"(a[2]), "r"(a[3]), "r"(b[0]), "r"(b[1]));
}

__global__ __launch_bounds__(256) void gemm_kernel() {
    __shared__ __align__(16) __nv_bfloat16 sA[2][128 * 40];
    __shared__ __align__(16) __nv_bfloat16 sB[2][128 * 40];
    const int mt = blockIdx.y, nt = blockIdx.x;
    const int tid = threadIdx.x;
    const int lane = tid & 31, warp = tid >> 5;
    const int wm = warp >> 1, wn = warp & 1;

    float acc[2][8][4];
#pragma unroll
    for (int a = 0; a < 2; a++)
#pragma unroll
        for (int b = 0; b < 8; b++)
#pragma unroll
            for (int c = 0; c < 4; c++) acc[a][b][c] = 0.f;

    auto load_tiles = [&](int buf, int k0) {
#pragma unroll
        for (int u = 0; u < 2; ++u) {
            int ch = tid + u * 256;
            int row = ch >> 2, c4 = ch & 3;
            cpa16(&sA[buf][row * 40 + c4 * 8],
                  g_Xt + (size_t)(mt * 128 + row) * CCH + k0 + c4 * 8);
            cpa16(&sB[buf][row * 40 + c4 * 8],
                  g_Yt + (size_t)(nt * 128 + row) * CCH + k0 + c4 * 8);
        }
        asm volatile("cp.async.commit_group;");
    };

    load_tiles(0, 0);
    const int NKI = CCH / 32;  // 8
    for (int kk = 0; kk < NKI; ++kk) {
        int buf = kk & 1;
        if (kk + 1 < NKI) {
            load_tiles(buf ^ 1, (kk + 1) * 32);
            asm volatile("cp.async.wait_group 1;");
        } else {
            asm volatile("cp.async.wait_group 0;");
        }
        __syncthreads();
#pragma unroll
        for (int ks = 0; ks < 2; ++ks) {
            uint32_t afr[2][4];
#pragma unroll
            for (int mi = 0; mi < 2; ++mi) {
                int r = wm * 32 + mi * 16 + (lane & 7) + ((lane >> 3) & 1) * 8;
                int cch = ks * 2 + (lane >> 4);
                ldsm4(afr[mi], &sA[buf][r * 40 + cch * 8]);
            }
            uint32_t bfr[8][2];
#pragma unroll
            for (int ni = 0; ni < 8; ++ni) {
                int l = lane & 15;
                int r = wn * 64 + ni * 8 + (l & 7);
                int cch = ks * 2 + ((l >> 3) & 1);
                ldsm2(bfr[ni], &sB[buf][r * 40 + cch * 8]);
            }
#pragma unroll
            for (int mi = 0; mi < 2; ++mi)
#pragma unroll
                for (int ni = 0; ni < 8; ++ni)
                    mma16816(acc[mi][ni], afr[mi], bfr[ni]);
        }
        __syncthreads();
    }

    // Epilogue: stream the tile to g_P
#pragma unroll
    for (int mi = 0; mi < 2; ++mi) {
#pragma unroll
        for (int ni = 0; ni < 8; ++ni) {
            int r0 = mt * 128 + wm * 32 + mi * 16 + (lane >> 2);
            int c0 = nt * 128 + wn * 64 + ni * 8 + (lane & 3) * 2;
            float2 v01 = make_float2(acc[mi][ni][0], acc[mi][ni][1]);
            float2 v23 = make_float2(acc[mi][ni][2], acc[mi][ni][3]);
            *reinterpret_cast<float2*>(&g_P[(size_t)r0 * NPIX + c0]) = v01;
            *reinterpret_cast<float2*>(&g_P[(size_t)(r0 + 8) * NPIX + c0]) = v23;
        }
    }
}

// ---------------------------------------------------------------------------
// K2: fused 9-tap diagonal sum + invnorm scale + argmax.
// resp[q=(i,j)][y=(u,v)] = sum_{delta} P[x+delta][y+delta],
// delta in {0,1,2,96,97,98,192,193,194}, x = i*96+j.
// One warp per q; lane scans 288 y positions (stride 32, coalesced per tap).
// Packed key (sortable(resp)<<32 | ~s) -> max = largest resp, then smallest s.
// ---------------------------------------------------------------------------
__global__ __launch_bounds__(256) void argmax_kernel() {
    int w = threadIdx.x >> 5, lane = threadIdx.x & 31;
    int qid = blockIdx.x * 8 + w;
    if (qid >= QN) return;
    int i = qid / OHW, j = qid % OHW;
    size_t xbase = (size_t)(i * WW + j);

    const float* rp[9];
#pragma unroll
    for (int t = 0; t < 9; ++t) {
        int dl = (t / 3) * WW + (t % 3);
        rp[t] = g_P + (xbase + dl) * NPIX + dl;   // rp[t][y] = P[x+dl][y+dl]
    }

    unsigned long long key = 0ull;
    for (int g = 0; g < NPIX / 32; ++g) {
        int y = g * 32 + lane;
        float inv = g_invY[y];
        float r = 0.f;
#pragma unroll
        for (int t = 0; t < 9; ++t) r += __ldg(rp[t] + y);
        float resp = r * inv;
        uint32_t uu = __float_as_uint(resp);
        uu ^= (uu >> 31) ? 0xFFFFFFFFu : 0x80000000u;
        int s = (y / WW) * OHW + (y % WW);    // style index; only meaningful if inv!=0
        unsigned long long kk = ((unsigned long long)uu << 32) |
                                (unsigned long long)(0xFFFFFFFFu - (uint32_t)s);
        if (kk > key) key = kk;
    }
#pragma unroll
    for (int off = 16; off; off >>= 1) {
        unsigned long long o = __shfl_xor_sync(0xFFFFFFFFu, key, off);
        if (o > key) key = o;
    }
    if (lane == 0)
        g_nn[qid] = (int)(0xFFFFFFFFu - (uint32_t)(key & 0xFFFFFFFFull));
}

// ---------------------------------------------------------------------------
// K3: exact fp32 gathered MSE from the raw images (GEMM precision only ever
// touched the argmax, not the loss value).
// ---------------------------------------------------------------------------
__global__ void loss_kernel(const float* __restrict__ inp, const float* __restrict__ tgt) {
    int q = blockIdx.x;       // < QN
    int tid = threadIdx.x;    // 256
    int snn = g_nn[q];
    int i = q / OHW, j = q % OHW;
    int u = snn / OHW, v = snn % OHW;
    float sum = 0.f;
#pragma unroll
    for (int it = 0; it < 9; ++it) {
        int d = it * 256 + tid;
        int c = d / 9, t = d - c * 9;
        int oa = c * (HH * WW) + (i + t / 3) * WW + (j + t % 3);
        int ob = c * (HH * WW) + (u + t / 3) * WW + (v + t % 3);
        float df = inp[oa] - tgt[ob];
        sum += df * df;
    }
    __shared__ float red[256];
    red[tid] = sum;
    __syncthreads();
    for (int s = 128; s > 0; s >>= 1) {
        if (tid < s) red[tid] += red[tid + s];
        __syncthreads();
    }
    if (tid == 0) g_loss[q] = red[0];
}

// K4: deterministic scalar reduce -> loss = sum / (QN * 2304)
__global__ void final_kernel(float* __restrict__ out) {
    __shared__ float red[256];
    int tid = threadIdx.x;
    float acc = 0.f;
    for (int i = tid; i < QN; i += 256) acc += g_loss[i];
    red[tid] = acc;
    __syncthreads();
    for (int s = 128; s > 0; s >>= 1) {
        if (tid < s) red[tid] += red[tid + s];
        __syncthreads();
    }
    if (tid == 0) out[0] = red[0] / ((float)QN * 2304.0f);
}

extern "C" void kernel_launch(void* const* d_in, const int* in_sizes, int n_in,
                              void* d_out, int out_size) {
    const float* inp = (const float*)d_in[0];   // input
    const float* tgt = (const float*)d_in[1];   // target
    float* out = (float*)d_out;

    dim3 tg(NPIX / 32, CCH / 32, 2);
    transpose_kernel<<<tg, 256>>>(inp, tgt);
    invnorm_kernel<<<QN, 256>>>();
    dim3 gg(MTIL, MTIL);
    gemm_kernel<<<gg, 256>>>();
    argmax_kernel<<<(QN + 7) / 8, 256>>>();
    loss_kernel<<<QN, 256>>>(inp, tgt);
    final_kernel<<<1, 256>>>(out);
}

// round 5
// speedup vs baseline: 3.1912x; 1.1296x over previous
#include <cuda_runtime.h>
#include <cuda_bf16.h>
#include <cstdint>

// Problem constants
#define HH 96
#define WW 96
#define NPIX 9216          // 96*96
#define OHW 94
#define QN 8836            // 94*94 patches on each side
#define CCH 256            // channels = GEMM K
#define MTIL 72            // 9216 / 128

// Static device scratch (no runtime allocation)
__device__ __nv_bfloat16 g_Xt[(size_t)NPIX * CCH];     // inp transposed  [pix][c] bf16
__device__ __nv_bfloat16 g_Yt[(size_t)NPIX * CCH];     // tgt transposed  [pix][c] bf16
__device__ __nv_bfloat16 g_Pb[(size_t)NPIX * NPIX + 256]; // pixel Gram matrix, bf16 (+tap pad)
__device__ float g_invY[NPIX];                         // 1/style_norm by y (0 if invalid)
__device__ int   g_nn[QN];
__device__ float g_loss[QN];

// ---------------------------------------------------------------------------
// K0: transpose+convert images: [256][9216] fp32 -> [9216][256] bf16
// ---------------------------------------------------------------------------
__global__ void transpose_kernel(const float* __restrict__ inp, const float* __restrict__ tgt) {
    __shared__ float t[32][33];
    const float* src = blockIdx.z ? tgt : inp;
    __nv_bfloat16* dst = blockIdx.z ? g_Yt : g_Xt;
    int p0 = blockIdx.x * 32, c0 = blockIdx.y * 32;
    int tx = threadIdx.x & 31, ty = threadIdx.x >> 5;  // 32 x 8
#pragma unroll
    for (int r = 0; r < 4; ++r) {
        int c = c0 + ty + r * 8;
        t[ty + r * 8][tx] = src[(size_t)c * NPIX + p0 + tx];
    }
    __syncthreads();
#pragma unroll
    for (int r = 0; r < 4; ++r) {
        int p = p0 + ty + r * 8;
        dst[(size_t)p * CCH + c0 + tx] = __float2bfloat16(t[tx][ty + r * 8]);
    }
}

// ---------------------------------------------------------------------------
// K0b: style patch inverse norms -> g_invY[y], y = u*96+v (0 elsewhere;
// zero-init at module load, invalid slots never written)
// ---------------------------------------------------------------------------
__global__ void invnorm_kernel() {
    int q = blockIdx.x;            // 0..QN-1
    int tid = threadIdx.x;         // 256 = one channel each
    int u = q / OHW, v = q % OHW;
    int y = u * WW + v;
    float ss = 0.f;
#pragma unroll
    for (int t = 0; t < 9; ++t) {
        int pix = y + (t / 3) * WW + (t % 3);
        float val = __bfloat162float(g_Yt[(size_t)pix * CCH + tid]);
        ss += val * val;
    }
    __shared__ float red[256];
    red[tid] = ss;
    __syncthreads();
    for (int s = 128; s > 0; s >>= 1) {
        if (tid < s) red[tid] += red[tid + s];
        __syncthreads();
    }
    if (tid == 0) g_invY[y] = 1.0f / sqrtf(red[0]);
}

// ---------------------------------------------------------------------------
// K1: P = Xt * Yt^T  (9216x9216x256 bf16 -> bf16). 128x128 tile, k-chunk 32,
// double-buffered cp.async, 8 warps. (validated HMMA pipeline)
// ---------------------------------------------------------------------------
__device__ __forceinline__ void cpa16(void* s, const void* g) {
    uint32_t sa = (uint32_t)__cvta_generic_to_shared(s);
    asm volatile("cp.async.cg.shared.global [%0], [%1], 16;" :: "r"(sa), "l"(g));
}
__device__ __forceinline__ void ldsm4(uint32_t* r, const __nv_bfloat16* p) {
    uint32_t sa = (uint32_t)__cvta_generic_to_shared(p);
    asm volatile("ldmatrix.sync.aligned.m8n8.x4.shared.b16 {%0,%1,%2,%3}, [%4];"
                 : "=r"(r[0]), "=r"(r[1]), "=r"(r[2]), "=r"(r[3]) : "r"(sa));
}
__device__ __forceinline__ void ldsm2(uint32_t* r, const __nv_bfloat16* p) {
    uint32_t sa = (uint32_t)__cvta_generic_to_shared(p);
    asm volatile("ldmatrix.sync.aligned.m8n8.x2.shared.b16 {%0,%1}, [%2];"
                 : "=r"(r[0]), "=r"(r[1]) : "r"(sa));
}
__device__ __forceinline__ void mma16816(float* c, const uint32_t* a, const uint32_t* b) {
    asm volatile(
        "mma.sync.aligned.m16n8k16.row.col.f32.bf16.bf16.f32 "
        "{%0,%1,%2,%3}, {%4,%5,%6,%7}, {%8,%9}, {%0,%1,%2,%3};"
        : "+f"(c[0]), "+f"(c[1]), "+f"(c[2]), "+f"(c[3])
        : "r"(a[0]), "r"(a[1]), "r"(a[2]), "r"(a[3]), "r"(b[0]), "r"(b[1]));
}

__global__ __launch_bounds__(256) void gemm_kernel() {
    __shared__ __align__(16) __nv_bfloat16 sA[2][128 * 40];
    __shared__ __align__(16) __nv_bfloat16 sB[2][128 * 40];
    const int mt = blockIdx.y, nt = blockIdx.x;
    const int tid = threadIdx.x;
    const int lane = tid & 31, warp = tid >> 5;
    const int wm = warp >> 1, wn = warp & 1;

    float acc[2][8][4];
#pragma unroll
    for (int a = 0; a < 2; a++)
#pragma unroll
        for (int b = 0; b < 8; b++)
#pragma unroll
            for (int c = 0; c < 4; c++) acc[a][b][c] = 0.f;

    auto load_tiles = [&](int buf, int k0) {
#pragma unroll
        for (int u = 0; u < 2; ++u) {
            int ch = tid + u * 256;
            int row = ch >> 2, c4 = ch & 3;
            cpa16(&sA[buf][row * 40 + c4 * 8],
                  g_Xt + (size_t)(mt * 128 + row) * CCH + k0 + c4 * 8);
            cpa16(&sB[buf][row * 40 + c4 * 8],
                  g_Yt + (size_t)(nt * 128 + row) * CCH + k0 + c4 * 8);
        }
        asm volatile("cp.async.commit_group;");
    };

    load_tiles(0, 0);
    const int NKI = CCH / 32;  // 8
    for (int kk = 0; kk < NKI; ++kk) {
        int buf = kk & 1;
        if (kk + 1 < NKI) {
            load_tiles(buf ^ 1, (kk + 1) * 32);
            asm volatile("cp.async.wait_group 1;");
        } else {
            asm volatile("cp.async.wait_group 0;");
        }
        __syncthreads();
#pragma unroll
        for (int ks = 0; ks < 2; ++ks) {
            uint32_t afr[2][4];
#pragma unroll
            for (int mi = 0; mi < 2; ++mi) {
                int r = wm * 32 + mi * 16 + (lane & 7) + ((lane >> 3) & 1) * 8;
                int cch = ks * 2 + (lane >> 4);
                ldsm4(afr[mi], &sA[buf][r * 40 + cch * 8]);
            }
            uint32_t bfr[8][2];
#pragma unroll
            for (int ni = 0; ni < 8; ++ni) {
                int l = lane & 15;
                int r = wn * 64 + ni * 8 + (l & 7);
                int cch = ks * 2 + ((l >> 3) & 1);
                ldsm2(bfr[ni], &sB[buf][r * 40 + cch * 8]);
            }
#pragma unroll
            for (int mi = 0; mi < 2; ++mi)
#pragma unroll
                for (int ni = 0; ni < 8; ++ni)
                    mma16816(acc[mi][ni], afr[mi], bfr[ni]);
        }
        __syncthreads();
    }

    // Epilogue: convert to bf16 pairs and stream to g_Pb (coalesced 4B/lane)
#pragma unroll
    for (int mi = 0; mi < 2; ++mi) {
#pragma unroll
        for (int ni = 0; ni < 8; ++ni) {
            int r0 = mt * 128 + wm * 32 + mi * 16 + (lane >> 2);
            int c0 = nt * 128 + wn * 64 + ni * 8 + (lane & 3) * 2;
            __nv_bfloat162 v01 = __floats2bfloat162_rn(acc[mi][ni][0], acc[mi][ni][1]);
            __nv_bfloat162 v23 = __floats2bfloat162_rn(acc[mi][ni][2], acc[mi][ni][3]);
            *reinterpret_cast<__nv_bfloat162*>(&g_Pb[(size_t)r0 * NPIX + c0]) = v01;
            *reinterpret_cast<__nv_bfloat162*>(&g_Pb[(size_t)(r0 + 8) * NPIX + c0]) = v23;
        }
    }
}

// ---------------------------------------------------------------------------
// K2: fused 9-tap diagonal sum + invnorm scale + argmax, vectorized on bf16 P.
// resp[q=(i,j)][y] = sum_t P[x+dl_t][y+dl_t],  dl = (t/3)*96 + (t%3), x=i*96+j.
// One warp per q; lane owns 8 consecutive y per iteration (warp: 256 y).
// Tap alignment: dl mod 8 = t%3 in {0,1,2}; fix with shfl + byte_perm.
// bf16->f32 unpack is exact: lo = w<<16, hi = w & 0xFFFF0000.
// ---------------------------------------------------------------------------
__global__ __launch_bounds__(256) void argmax_kernel() {
    int w = threadIdx.x >> 5, lane = threadIdx.x & 31;
    int qid = blockIdx.x * 8 + w;
    if (qid >= QN) return;
    int i = qid / OHW, j = qid % OHW;
    int x = i * WW + j;

    const __nv_bfloat16* tp[9];
#pragma unroll
    for (int t = 0; t < 9; ++t) {
        int dl = (t / 3) * WW + (t % 3);
        int o = t % 3;
        tp[t] = g_Pb + (size_t)(x + dl) * NPIX + (dl - o) + lane * 8;
    }

    unsigned long long key = 0ull;
#pragma unroll 1
    for (int g = 0; g < NPIX / 256; ++g) {   // 36 iterations
        const int ybase = g * 256 + lane * 8;
        float r[8];
#pragma unroll
        for (int e = 0; e < 8; ++e) r[e] = 0.f;

#pragma unroll
        for (int t = 0; t < 9; ++t) {
            const __nv_bfloat16* p = tp[t] + g * 256;
            uint4 ch = __ldg(reinterpret_cast<const uint4*>(p));
            uint32_t n0 = __shfl_down_sync(0xFFFFFFFFu, ch.x, 1);
            if (lane == 31) n0 = __ldg(reinterpret_cast<const uint32_t*>(p + 8));
            uint32_t w0, w1, w2, w3;
            const int o = t % 3;
            if (o == 0)      { w0 = ch.x; w1 = ch.y; w2 = ch.z; w3 = ch.w; }
            else if (o == 2) { w0 = ch.y; w1 = ch.z; w2 = ch.w; w3 = n0; }
            else {
                w0 = __byte_perm(ch.x, ch.y, 0x5432);
                w1 = __byte_perm(ch.y, ch.z, 0x5432);
                w2 = __byte_perm(ch.z, ch.w, 0x5432);
                w3 = __byte_perm(ch.w, n0,   0x5432);
            }
            r[0] += __uint_as_float(w0 << 16);
            r[1] += __uint_as_float(w0 & 0xFFFF0000u);
            r[2] += __uint_as_float(w1 << 16);
            r[3] += __uint_as_float(w1 & 0xFFFF0000u);
            r[4] += __uint_as_float(w2 << 16);
            r[5] += __uint_as_float(w2 & 0xFFFF0000u);
            r[6] += __uint_as_float(w3 << 16);
            r[7] += __uint_as_float(w3 & 0xFFFF0000u);
        }

        float4 i0 = __ldg(reinterpret_cast<const float4*>(&g_invY[ybase]));
        float4 i1 = __ldg(reinterpret_cast<const float4*>(&g_invY[ybase + 4]));
        float iv[8] = {i0.x, i0.y, i0.z, i0.w, i1.x, i1.y, i1.z, i1.w};
#pragma unroll
        for (int e = 0; e < 8; ++e) {
            float resp = r[e] * iv[e];
            uint32_t uu = __float_as_uint(resp);
            uu ^= (uu >> 31) ? 0xFFFFFFFFu : 0x80000000u;
            unsigned long long kk = ((unsigned long long)uu << 32) |
                                    (unsigned long long)(0xFFFFFFFFu - (uint32_t)(ybase + e));
            if (kk > key) key = kk;
        }
    }
#pragma unroll
    for (int off = 16; off; off >>= 1) {
        unsigned long long o = __shfl_xor_sync(0xFFFFFFFFu, key, off);
        if (o > key) key = o;
    }
    if (lane == 0) {
        int y = (int)(0xFFFFFFFFu - (uint32_t)(key & 0xFFFFFFFFull));
        g_nn[qid] = (y / WW) * OHW + (y % WW);
    }
}

// ---------------------------------------------------------------------------
// K3: exact fp32 gathered MSE from the raw images (GEMM/bf16 precision only
// ever touched the argmax, not the loss value).
// ---------------------------------------------------------------------------
__global__ void loss_kernel(const float* __restrict__ inp, const float* __restrict__ tgt) {
    int q = blockIdx.x;       // < QN
    int tid = threadIdx.x;    // 256
    int snn = g_nn[q];
    int i = q / OHW, j = q % OHW;
    int u = snn / OHW, v = snn % OHW;
    float sum = 0.f;
#pragma unroll
    for (int it = 0; it < 9; ++it) {
        int d = it * 256 + tid;
        int c = d / 9, t = d - c * 9;
        int oa = c * (HH * WW) + (i + t / 3) * WW + (j + t % 3);
        int ob = c * (HH * WW) + (u + t / 3) * WW + (v + t % 3);
        float df = inp[oa] - tgt[ob];
        sum += df * df;
    }
    __shared__ float red[256];
    red[tid] = sum;
    __syncthreads();
    for (int s = 128; s > 0; s >>= 1) {
        if (tid < s) red[tid] += red[tid + s];
        __syncthreads();
    }
    if (tid == 0) g_loss[q] = red[0];
}

// K4: deterministic scalar reduce -> loss = sum / (QN * 2304)
__global__ void final_kernel(float* __restrict__ out) {
    __shared__ float red[256];
    int tid = threadIdx.x;
    float acc = 0.f;
    for (int i = tid; i < QN; i += 256) acc += g_loss[i];
    red[tid] = acc;
    __syncthreads();
    for (int s = 128; s > 0; s >>= 1) {
        if (tid < s) red[tid] += red[tid + s];
        __syncthreads();
    }
    if (tid == 0) out[0] = red[0] / ((float)QN * 2304.0f);
}

extern "C" void kernel_launch(void* const* d_in, const int* in_sizes, int n_in,
                              void* d_out, int out_size) {
    const float* inp = (const float*)d_in[0];   // input
    const float* tgt = (const float*)d_in[1];   // target
    float* out = (float*)d_out;

    dim3 tg(NPIX / 32, CCH / 32, 2);
    transpose_kernel<<<tg, 256>>>(inp, tgt);
    invnorm_kernel<<<QN, 256>>>();
    dim3 gg(MTIL, MTIL);
    gemm_kernel<<<gg, 256>>>();
    argmax_kernel<<<(QN + 7) / 8, 256>>>();
    loss_kernel<<<QN, 256>>>(inp, tgt);
    final_kernel<<<1, 256>>>(out);
}

// round 6
// speedup vs baseline: 3.7076x; 1.1618x over previous
#include <cuda_runtime.h>
#include <cuda_bf16.h>
#include <cstdint>

// Problem constants
#define HH 96
#define WW 96
#define NPIX 9216          // 96*96
#define OHW 94
#define QN 8836            // 94*94 patches on each side
#define CCH 256            // channels = GEMM K
#define MTIL 72            // 9216 / 128

// Static device scratch (no runtime allocation)
__device__ __nv_bfloat16 g_Xt[(size_t)NPIX * CCH];     // inp transposed  [pix][c] bf16
__device__ __nv_bfloat16 g_Yt[(size_t)NPIX * CCH];     // tgt transposed  [pix][c] bf16
__device__ __nv_bfloat16 g_Pb[(size_t)NPIX * NPIX + 256]; // pixel Gram matrix, bf16 (+tap pad)
__device__ float g_invY[NPIX];                         // 1/style_norm by y (0 if invalid)
__device__ int   g_nn[QN];
__device__ float g_loss[QN];

// ---------------------------------------------------------------------------
// K0: transpose+convert images: [256][9216] fp32 -> [9216][256] bf16
// ---------------------------------------------------------------------------
__global__ void transpose_kernel(const float* __restrict__ inp, const float* __restrict__ tgt) {
    __shared__ float t[32][33];
    const float* src = blockIdx.z ? tgt : inp;
    __nv_bfloat16* dst = blockIdx.z ? g_Yt : g_Xt;
    int p0 = blockIdx.x * 32, c0 = blockIdx.y * 32;
    int tx = threadIdx.x & 31, ty = threadIdx.x >> 5;  // 32 x 8
#pragma unroll
    for (int r = 0; r < 4; ++r) {
        int c = c0 + ty + r * 8;
        t[ty + r * 8][tx] = src[(size_t)c * NPIX + p0 + tx];
    }
    __syncthreads();
#pragma unroll
    for (int r = 0; r < 4; ++r) {
        int p = p0 + ty + r * 8;
        dst[(size_t)p * CCH + c0 + tx] = __float2bfloat16(t[tx][ty + r * 8]);
    }
}

// ---------------------------------------------------------------------------
// K0b: style patch inverse norms -> g_invY[y], y = u*96+v (0 elsewhere;
// zero-init at module load, invalid slots never written)
// ---------------------------------------------------------------------------
__global__ void invnorm_kernel() {
    int q = blockIdx.x;            // 0..QN-1
    int tid = threadIdx.x;         // 256 = one channel each
    int u = q / OHW, v = q % OHW;
    int y = u * WW + v;
    float ss = 0.f;
#pragma unroll
    for (int t = 0; t < 9; ++t) {
        int pix = y + (t / 3) * WW + (t % 3);
        float val = __bfloat162float(g_Yt[(size_t)pix * CCH + tid]);
        ss += val * val;
    }
    __shared__ float red[256];
    red[tid] = ss;
    __syncthreads();
    for (int s = 128; s > 0; s >>= 1) {
        if (tid < s) red[tid] += red[tid + s];
        __syncthreads();
    }
    if (tid == 0) g_invY[y] = 1.0f / sqrtf(red[0]);
}

// ---------------------------------------------------------------------------
// K1: P = Xt * Yt^T  (9216x9216x256 bf16 -> bf16). 128x128 tile, k-chunk 32,
// double-buffered cp.async, 8 warps. (validated HMMA pipeline)
// ---------------------------------------------------------------------------
__device__ __forceinline__ void cpa16(void* s, const void* g) {
    uint32_t sa = (uint32_t)__cvta_generic_to_shared(s);
    asm volatile("cp.async.cg.shared.global [%0], [%1], 16;" :: "r"(sa), "l"(g));
}
__device__ __forceinline__ void ldsm4(uint32_t* r, const __nv_bfloat16* p) {
    uint32_t sa = (uint32_t)__cvta_generic_to_shared(p);
    asm volatile("ldmatrix.sync.aligned.m8n8.x4.shared.b16 {%0,%1,%2,%3}, [%4];"
                 : "=r"(r[0]), "=r"(r[1]), "=r"(r[2]), "=r"(r[3]) : "r"(sa));
}
__device__ __forceinline__ void ldsm2(uint32_t* r, const __nv_bfloat16* p) {
    uint32_t sa = (uint32_t)__cvta_generic_to_shared(p);
    asm volatile("ldmatrix.sync.aligned.m8n8.x2.shared.b16 {%0,%1}, [%2];"
                 : "=r"(r[0]), "=r"(r[1]) : "r"(sa));
}
__device__ __forceinline__ void mma16816(float* c, const uint32_t* a, const uint32_t* b) {
    asm volatile(
        "mma.sync.aligned.m16n8k16.row.col.f32.bf16.bf16.f32 "
        "{%0,%1,%2,%3}, {%4,%5,%6,%7}, {%8,%9}, {%0,%1,%2,%3};"
        : "+f"(c[0]), "+f"(c[1]), "+f"(c[2]), "+f"(c[3])
        : "r"(a[0]), "r"(a[1]), "r"(a[2]), "r"(a[3]), "r"(b[0]), "r"(b[1]));
}

__global__ __launch_bounds__(256) void gemm_kernel() {
    __shared__ __align__(16) __nv_bfloat16 sA[2][128 * 40];
    __shared__ __align__(16) __nv_bfloat16 sB[2][128 * 40];
    const int mt = blockIdx.y, nt = blockIdx.x;
    const int tid = threadIdx.x;
    const int lane = tid & 31, warp = tid >> 5;
    const int wm = warp >> 1, wn = warp & 1;

    float acc[2][8][4];
#pragma unroll
    for (int a = 0; a < 2; a++)
#pragma unroll
        for (int b = 0; b < 8; b++)
#pragma unroll
            for (int c = 0; c < 4; c++) acc[a][b][c] = 0.f;

    auto load_tiles = [&](int buf, int k0) {
#pragma unroll
        for (int u = 0; u < 2; ++u) {
            int ch = tid + u * 256;
            int row = ch >> 2, c4 = ch & 3;
            cpa16(&sA[buf][row * 40 + c4 * 8],
                  g_Xt + (size_t)(mt * 128 + row) * CCH + k0 + c4 * 8);
            cpa16(&sB[buf][row * 40 + c4 * 8],
                  g_Yt + (size_t)(nt * 128 + row) * CCH + k0 + c4 * 8);
        }
        asm volatile("cp.async.commit_group;");
    };

    load_tiles(0, 0);
    const int NKI = CCH / 32;  // 8
    for (int kk = 0; kk < NKI; ++kk) {
        int buf = kk & 1;
        if (kk + 1 < NKI) {
            load_tiles(buf ^ 1, (kk + 1) * 32);
            asm volatile("cp.async.wait_group 1;");
        } else {
            asm volatile("cp.async.wait_group 0;");
        }
        __syncthreads();
#pragma unroll
        for (int ks = 0; ks < 2; ++ks) {
            uint32_t afr[2][4];
#pragma unroll
            for (int mi = 0; mi < 2; ++mi) {
                int r = wm * 32 + mi * 16 + (lane & 7) + ((lane >> 3) & 1) * 8;
                int cch = ks * 2 + (lane >> 4);
                ldsm4(afr[mi], &sA[buf][r * 40 + cch * 8]);
            }
            uint32_t bfr[8][2];
#pragma unroll
            for (int ni = 0; ni < 8; ++ni) {
                int l = lane & 15;
                int r = wn * 64 + ni * 8 + (l & 7);
                int cch = ks * 2 + ((l >> 3) & 1);
                ldsm2(bfr[ni], &sB[buf][r * 40 + cch * 8]);
            }
#pragma unroll
            for (int mi = 0; mi < 2; ++mi)
#pragma unroll
                for (int ni = 0; ni < 8; ++ni)
                    mma16816(acc[mi][ni], afr[mi], bfr[ni]);
        }
        __syncthreads();
    }

    // Epilogue: convert to bf16 pairs and stream to g_Pb (coalesced 4B/lane)
#pragma unroll
    for (int mi = 0; mi < 2; ++mi) {
#pragma unroll
        for (int ni = 0; ni < 8; ++ni) {
            int r0 = mt * 128 + wm * 32 + mi * 16 + (lane >> 2);
            int c0 = nt * 128 + wn * 64 + ni * 8 + (lane & 3) * 2;
            __nv_bfloat162 v01 = __floats2bfloat162_rn(acc[mi][ni][0], acc[mi][ni][1]);
            __nv_bfloat162 v23 = __floats2bfloat162_rn(acc[mi][ni][2], acc[mi][ni][3]);
            *reinterpret_cast<__nv_bfloat162*>(&g_Pb[(size_t)r0 * NPIX + c0]) = v01;
            *reinterpret_cast<__nv_bfloat162*>(&g_Pb[(size_t)(r0 + 8) * NPIX + c0]) = v23;
        }
    }
}

// ---------------------------------------------------------------------------
// K2: fused 9-tap diagonal sum + invnorm scale + argmax on bf16 P.
// resp[q=(i,j)][y] = sum_t P[x+dl_t][y+dl_t], dl = (t/3)*96 + (t%3), x=i*96+j.
// Taps grouped by column offset o = t%3: each group accumulated PACKED in
// bf16x2 (no per-tap realign); realignment done once per group per iteration
// (o=1: shfl+byte_perm; o=2: shfl+word rotate). Groups combined in fp32.
// One warp per q; lane owns 8 consecutive y per iteration (warp: 256 y).
// ---------------------------------------------------------------------------
__device__ __forceinline__ uint32_t badd2(uint32_t a, uint32_t b) {
    __nv_bfloat162 av, bv;
    *reinterpret_cast<uint32_t*>(&av) = a;
    *reinterpret_cast<uint32_t*>(&bv) = b;
    __nv_bfloat162 rv = __hadd2(av, bv);
    return *reinterpret_cast<uint32_t*>(&rv);
}

__global__ __launch_bounds__(256) void argmax_kernel() {
    int w = threadIdx.x >> 5, lane = threadIdx.x & 31;
    int qid = blockIdx.x * 8 + w;
    if (qid >= QN) return;
    int i = qid / OHW, j = qid % OHW;
    int x = i * WW + j;

    // Aligned row bases per tap: base column = dl - o (multiple of 8 elems).
    const __nv_bfloat16* tp[9];
#pragma unroll
    for (int t = 0; t < 9; ++t) {
        int dl = (t / 3) * WW + (t % 3);
        tp[t] = g_Pb + (size_t)(x + dl) * NPIX + (dl - (t % 3));
    }

    float best = -3.0e38f;
    int bestY = 0;

#pragma unroll 1
    for (int g = 0; g < NPIX / 256; ++g) {   // 36 iterations
        const int off = g * 256 + lane * 8;  // element offset from aligned base
        const int ybase = off;               // y of element e = ybase + e

        uint4 A0 = {0u, 0u, 0u, 0u}, A1 = A0, A2 = A0;
        uint32_t nA1 = 0u, nA2 = 0u;         // lane-31 boundary accumulators

#pragma unroll
        for (int t = 0; t < 9; ++t) {
            uint4 ch = __ldg(reinterpret_cast<const uint4*>(tp[t] + off));
            const int o = t % 3;
            if (o == 0) {
                A0.x = badd2(A0.x, ch.x); A0.y = badd2(A0.y, ch.y);
                A0.z = badd2(A0.z, ch.z); A0.w = badd2(A0.w, ch.w);
            } else if (o == 1) {
                A1.x = badd2(A1.x, ch.x); A1.y = badd2(A1.y, ch.y);
                A1.z = badd2(A1.z, ch.z); A1.w = badd2(A1.w, ch.w);
                if (lane == 31)
                    nA1 = badd2(nA1, __ldg(reinterpret_cast<const uint32_t*>(tp[t] + off + 8)));
            } else {
                A2.x = badd2(A2.x, ch.x); A2.y = badd2(A2.y, ch.y);
                A2.z = badd2(A2.z, ch.z); A2.w = badd2(A2.w, ch.w);
                if (lane == 31)
                    nA2 = badd2(nA2, __ldg(reinterpret_cast<const uint32_t*>(tp[t] + off + 8)));
            }
        }

        // Boundary words: next lane's first packed word (covers elements 8,9).
        uint32_t n1 = __shfl_down_sync(0xFFFFFFFFu, A1.x, 1);
        uint32_t n2 = __shfl_down_sync(0xFFFFFFFFu, A2.x, 1);
        if (lane == 31) { n1 = nA1; n2 = nA2; }

        // Realign group1 by 1 element (2 bytes), group2 by 2 elements (1 word).
        uint32_t b1[4], b2[4];
        b1[0] = __byte_perm(A1.x, A1.y, 0x5432);
        b1[1] = __byte_perm(A1.y, A1.z, 0x5432);
        b1[2] = __byte_perm(A1.z, A1.w, 0x5432);
        b1[3] = __byte_perm(A1.w, n1,   0x5432);
        b2[0] = A2.y; b2[1] = A2.z; b2[2] = A2.w; b2[3] = n2;

        // Combine groups in fp32, scale, compare.
        float4 i0 = __ldg(reinterpret_cast<const float4*>(&g_invY[ybase]));
        float4 i1 = __ldg(reinterpret_cast<const float4*>(&g_invY[ybase + 4]));
        const float iv[8] = {i0.x, i0.y, i0.z, i0.w, i1.x, i1.y, i1.z, i1.w};
        const uint32_t a0w[4] = {A0.x, A0.y, A0.z, A0.w};
#pragma unroll
        for (int wi = 0; wi < 4; ++wi) {
            float lo = __uint_as_float(a0w[wi] << 16) +
                       __uint_as_float(b1[wi] << 16) +
                       __uint_as_float(b2[wi] << 16);
            float hi = __uint_as_float(a0w[wi] & 0xFFFF0000u) +
                       __uint_as_float(b1[wi] & 0xFFFF0000u) +
                       __uint_as_float(b2[wi] & 0xFFFF0000u);
            float r0 = lo * iv[wi * 2];
            float r1 = hi * iv[wi * 2 + 1];
            if (r0 > best) { best = r0; bestY = ybase + wi * 2; }
            if (r1 > best) { best = r1; bestY = ybase + wi * 2 + 1; }
        }
    }

    // Warp reduce: largest resp, tie -> smallest y (matches jnp.argmax).
#pragma unroll
    for (int offw = 16; offw; offw >>= 1) {
        float ob = __shfl_xor_sync(0xFFFFFFFFu, best, offw);
        int oy = __shfl_xor_sync(0xFFFFFFFFu, bestY, offw);
        if (ob > best || (ob == best && oy < bestY)) { best = ob; bestY = oy; }
    }
    if (lane == 0)
        g_nn[qid] = (bestY / WW) * OHW + (bestY % WW);
}

// ---------------------------------------------------------------------------
// K3: exact fp32 gathered MSE from the raw images (GEMM/bf16 precision only
// ever touched the argmax, not the loss value).
// ---------------------------------------------------------------------------
__global__ void loss_kernel(const float* __restrict__ inp, const float* __restrict__ tgt) {
    int q = blockIdx.x;       // < QN
    int tid = threadIdx.x;    // 256
    int snn = g_nn[q];
    int i = q / OHW, j = q % OHW;
    int u = snn / OHW, v = snn % OHW;
    float sum = 0.f;
#pragma unroll
    for (int it = 0; it < 9; ++it) {
        int d = it * 256 + tid;
        int c = d / 9, t = d - c * 9;
        int oa = c * (HH * WW) + (i + t / 3) * WW + (j + t % 3);
        int ob = c * (HH * WW) + (u + t / 3) * WW + (v + t % 3);
        float df = inp[oa] - tgt[ob];
        sum += df * df;
    }
    __shared__ float red[256];
    red[tid] = sum;
    __syncthreads();
    for (int s = 128; s > 0; s >>= 1) {
        if (tid < s) red[tid] += red[tid + s];
        __syncthreads();
    }
    if (tid == 0) g_loss[q] = red[0];
}

// K4: deterministic scalar reduce -> loss = sum / (QN * 2304)
__global__ void final_kernel(float* __restrict__ out) {
    __shared__ float red[1024];
    int tid = threadIdx.x;
    float acc = 0.f;
    for (int i = tid; i < QN; i += 1024) acc += g_loss[i];
    red[tid] = acc;
    __syncthreads();
    for (int s = 512; s > 0; s >>= 1) {
        if (tid < s) red[tid] += red[tid + s];
        __syncthreads();
    }
    if (tid == 0) out[0] = red[0] / ((float)QN * 2304.0f);
}

extern "C" void kernel_launch(void* const* d_in, const int* in_sizes, int n_in,
                              void* d_out, int out_size) {
    const float* inp = (const float*)d_in[0];   // input
    const float* tgt = (const float*)d_in[1];   // target
    float* out = (float*)d_out;

    dim3 tg(NPIX / 32, CCH / 32, 2);
    transpose_kernel<<<tg, 256>>>(inp, tgt);
    invnorm_kernel<<<QN, 256>>>();
    dim3 gg(MTIL, MTIL);
    gemm_kernel<<<gg, 256>>>();
    argmax_kernel<<<(QN + 7) / 8, 256>>>();
    loss_kernel<<<QN, 256>>>(inp, tgt);
    final_kernel<<<1, 1024>>>(out);
}